// round 1
// baseline (speedup 1.0000x reference)
#include <cuda_runtime.h>
#include <cuda_bf16.h>
#include <math.h>

#define CELLN 14
#define NCLS  80
#define BPC   3
#define FEAT  95            // 80 + 3 + 12
#define CELLS2 196          // 14*14
#define PRED_PER_B 18620    // 196*95
#define CSF   32.0f
#define IMGF  448.0f
#define EPSF  1e-9f
#define INV_PI2_4 0.40528473456935109f   // 4/pi^2

__device__ float g_batch_loss[4096];

// ---------------------------------------------------------------------------
// Kernel 1: one CTA per batch element.
// ---------------------------------------------------------------------------
__global__ __launch_bounds__(256, 2)
void yolo_loss_batch_kernel(const float* __restrict__ predicts,
                            const float* __restrict__ labels,
                            const int*   __restrict__ objects_num,
                            int M)
{
    extern __shared__ float smem[];
    float* sp     = smem;                    // [18620] predicts for this batch
    float* slab   = sp + PRED_PER_B;         // [M*5]   labels for this batch
    float* sumP2  = slab + M * 5;            // [196]   per-cell class sum of squares
    float* sred   = sumP2 + CELLS2;          // [8]     warp partials
    float* sS     = sred + 8;                // [1]     total conf sum-of-squares

    const int b    = blockIdx.x;
    const int tid  = threadIdx.x;
    const int lane = tid & 31;
    const int wid  = tid >> 5;

    // ---- stage predicts (74480 B) into smem, vectorized ----
    {
        const float4* src = (const float4*)(predicts + (size_t)b * PRED_PER_B);
        float4* dst = (float4*)sp;
        #pragma unroll 4
        for (int i = tid; i < PRED_PER_B / 4; i += 256) dst[i] = src[i];
    }
    for (int i = tid; i < M * 5; i += 256) slab[i] = labels[(size_t)b * M * 5 + i];
    __syncthreads();

    // ---- per-cell class sumsq + total confidence sumsq ----
    float confsq = 0.0f;
    for (int c = tid; c < CELLS2; c += 256) {
        const float* p = sp + c * FEAT;
        float s = 0.0f;
        #pragma unroll 10
        for (int k = 0; k < NCLS; k++) s += p[k] * p[k];
        sumP2[c] = s;
        float c0 = p[80], c1 = p[81], c2 = p[82];
        confsq += c0 * c0 + c1 * c1 + c2 * c2;
    }
    #pragma unroll
    for (int off = 16; off; off >>= 1)
        confsq += __shfl_xor_sync(0xFFFFFFFFu, confsq, off);
    if (lane == 0) sred[wid] = confsq;
    __syncthreads();
    if (tid == 0) {
        float s = 0.0f;
        #pragma unroll
        for (int i = 0; i < 8; i++) s += sred[i];
        sS[0] = s;
    }
    __syncthreads();
    const float S_pc2 = sS[0];
    __syncthreads();           // sred reused below for warp accumulators

    // ---- per-object work, one warp per object (strided) ----
    int nobj = objects_num[b];
    if (nobj > M) nobj = M;

    float wacc = 0.0f;
    for (int o = wid; o < nobj; o += 8) {
        const float* l = slab + o * 5;
        const float x = l[0], y = l[1], w = l[2], h = l[3];
        const int   k = (int)l[4];

        // object mask bounds (min_x is floor -> integer-valued)
        const int ix0 = (int)floorf((x - 0.5f * w) * (1.0f / CSF));
        const int ix1 = (int)fminf(ceilf((x + 0.5f * w) * (1.0f / CSF)), (float)CELLN);
        const int iy0 = (int)floorf((y - 0.5f * h) * (1.0f / CSF));
        const int iy1 = (int)fminf(ceilf((y + 0.5f * h) * (1.0f / CSF)), (float)CELLN);
        const int nx  = max(0, ix1 - ix0);
        const int ny  = max(0, iy1 - iy0);
        const int cnt = nx * ny;

        // class loss: sum over masked cells of (Σp² − 2 p_k + 1)
        float cls = 0.0f;
        for (int t = lane; t < cnt; t += 32) {
            const int iy = iy0 + t / nx;
            const int ix = ix0 + t % nx;
            const int cell = iy * CELLN + ix;
            cls += sumP2[cell] - 2.0f * sp[cell * FEAT + k] + 1.0f;
        }
        #pragma unroll
        for (int off = 16; off; off >>= 1)
            cls += __shfl_xor_sync(0xFFFFFFFFu, cls, off);

        // center cell
        const int cx = (int)floorf(x * (1.0f / CSF));
        const int cy = (int)floorf(y * (1.0f / CSF));
        const float* pc = sp + (cy * CELLN + cx) * FEAT;

        float ciou = -1e30f;
        float pC = 0.f, px = 0.f, py = 0.f, pw = 0.f, ph = 0.f;
        if (lane < BPC) {
            pC = pc[80 + lane];
            const float* bx = pc + 80 + BPC + 4 * lane;
            px = bx[0] * CSF + (float)cx * CSF;
            py = bx[1] * CSF + (float)cy * CSF;
            pw = bx[2] * IMGF;
            ph = bx[3] * IMGF;

            // ---- CIoU exactly per reference (incl. its enclose quirk) ----
            const float x11 = px - 0.5f * pw, x12 = px + 0.5f * pw;
            const float y11 = py - 0.5f * ph, y12 = py + 0.5f * ph;
            const float x21 = x - 0.5f * w,   x22 = x + 0.5f * w;
            const float y21 = y - 0.5f * h,   y22 = y + 0.5f * h;
            const float iw = fmaxf(fminf(x12, x22) - fmaxf(x11, x21), 0.0f);
            const float ih = fmaxf(fminf(y12, y22) - fmaxf(y11, y21), 0.0f);
            const float inter = iw * ih;
            const float uni = pw * ph + w * h - inter;
            const float iou = inter / (uni + EPSF);
            const float cd  = (px - x) * (px - x) + (py - y) * (py - y);
            // reference uses centers vs widths for the enclose box:
            const float el = fminf(px, x), er = fmaxf(pw, w);
            const float et = fminf(py, y), eb = fmaxf(ph, h);
            const float ed = (er - el) * (er - el) + (eb - et) * (eb - et);
            const float da = atanf(w / (h + EPSF)) - atanf(pw / (ph + EPSF));
            const float v  = INV_PI2_4 * da * da;
            const float alpha = v / (1.0f - iou + v + EPSF);
            ciou = iou - cd / (ed + EPSF) - alpha * v;
        }
        // max over the 3 boxes (lanes 0..3 form an XOR group; lane 3 = -inf)
        float m = ciou;
        m = fmaxf(m, __shfl_xor_sync(0xFFFFFFFFu, m, 1));
        m = fmaxf(m, __shfl_xor_sync(0xFFFFFFFFu, m, 2));

        float contrib = 0.0f;
        if (lane < BPC && ciou >= m) {
            const float d = pC - ciou;
            contrib += 0.5f * d * d;           // object loss (OBJECT_SCALE=1)
            contrib -= 0.25f * pC * pC;        // removed from noobject term
            const float dx = (px - x) * (1.0f / CSF);
            const float dy = (py - y) * (1.0f / CSF);
            const float swp = sqrtf(fminf(fmaxf(pw, 0.0f), IMGF));
            const float shp = sqrtf(fminf(fmaxf(ph, 0.0f), IMGF));
            const float sw = sqrtf(fabsf(w));
            const float sh = sqrtf(fabsf(h));
            const float dw = swp - sw, dh = shp - sh;
            contrib += 5.0f * (0.5f * dx * dx + 0.5f * dy * dy
                               + (0.5f * dw * dw) * (1.0f / IMGF)
                               + (0.5f * dh * dh) * (1.0f / IMGF));
        }
        contrib += __shfl_xor_sync(0xFFFFFFFFu, contrib, 1);
        contrib += __shfl_xor_sync(0xFFFFFFFFu, contrib, 2);

        if (lane == 0)
            wacc += 0.5f * cls + contrib + 0.25f * S_pc2;
    }

    if (lane == 0) sred[wid] = wacc;
    __syncthreads();
    if (tid == 0) {
        float s = 0.0f;
        #pragma unroll
        for (int i = 0; i < 8; i++) s += sred[i];
        g_batch_loss[b] = s;
    }
}

// ---------------------------------------------------------------------------
// Kernel 2: deterministic final reduction over batches.
// ---------------------------------------------------------------------------
__global__ void yolo_loss_reduce_kernel(float* __restrict__ out, int B)
{
    __shared__ float s[256];
    const int t = threadIdx.x;
    float a = 0.0f;
    for (int i = t; i < B; i += 256) a += g_batch_loss[i];
    s[t] = a;
    __syncthreads();
    #pragma unroll
    for (int off = 128; off; off >>= 1) {
        if (t < off) s[t] += s[t + off];
        __syncthreads();
    }
    if (t == 0) out[0] = s[0] / (float)B;
}

extern "C" void kernel_launch(void* const* d_in, const int* in_sizes, int n_in,
                              void* d_out, int out_size)
{
    const float* predicts = (const float*)d_in[0];
    const float* labels   = (const float*)d_in[1];
    const int*   objnum   = (const int*)d_in[2];
    float* out = (float*)d_out;

    const int B = in_sizes[2];
    const int M = in_sizes[1] / (B * 5);

    const int smem_bytes = (PRED_PER_B + M * 5 + CELLS2 + 8 + 1) * (int)sizeof(float);
    cudaFuncSetAttribute(yolo_loss_batch_kernel,
                         cudaFuncAttributeMaxDynamicSharedMemorySize, smem_bytes);

    yolo_loss_batch_kernel<<<B, 256, smem_bytes>>>(predicts, labels, objnum, M);
    yolo_loss_reduce_kernel<<<1, 256>>>(out, B);
}